// round 15
// baseline (speedup 1.0000x reference)
#include <cuda_runtime.h>
#include <cuda_bf16.h>
#include <math.h>

#define D_MODEL   1024
#define MEM_SIZE  131072
#define TOP_K     64
#define D_STATE   16
#define D_CONV    4
#define D_INNER   2048
#define DT_RANK   64
#define XPROJ_OUT (DT_RANK + 2*D_STATE)   // 96
#define L_SEQ     64
#define EPS_COS   1e-8f
#define EPS_LN    1e-5f
#define CAND_CAP  2048
#define NBLK      148
#define NTHR      512

// ---------------- scratch ----------------
__device__ float g_sims[MEM_SIZE];
__device__ unsigned int g_hist16[65536];
__device__ unsigned int g_coarse[512];
__device__ int g_p16;
__device__ unsigned int g_ccnt;
__device__ float g_cval[CAND_CAP];
__device__ int   g_cidx[CAND_CAP];
__device__ int   g_topk[TOP_K];
__device__ float g_uact[L_SEQ * D_INNER];
__device__ float g_z63[D_INNER];
__device__ float g_xdbl[L_SEQ * XPROJ_OUT];
__device__ float g_y[D_INNER];
__device__ float g_ctx[D_MODEL];
__device__ float g_sink[NBLK];
__device__ unsigned int g_bar_count;
__device__ unsigned int g_bar_gen;

__device__ __forceinline__ unsigned int fkey(float v) {
    unsigned int u = __float_as_uint(v);
    return (u & 0x80000000u) ? ~u : (u | 0x80000000u);
}
__device__ __forceinline__ bool before_pair(float va, int ia, float vb, int ib) {
    return (va > vb) || (va == vb && ia < ib);
}

__device__ __forceinline__ void gbar() {
    __syncthreads();
    __threadfence();
    if (threadIdx.x == 0) {
        volatile unsigned int* genp = &g_bar_gen;
        unsigned int gen = *genp;
        if (atomicAdd(&g_bar_count, 1u) == gridDim.x - 1) {
            g_bar_count = 0u;
            __threadfence();
            *genp = gen + 1u;
        } else {
            while (*genp == gen) { }
        }
    }
    __syncthreads();
}

// ---------------- K1: fused qnorm + cosine sims + 16-bit histogram ----------------
__global__ void k_sims(const float* __restrict__ mem, const float* __restrict__ q) {
    __shared__ __align__(16) float sq[D_MODEL];
    __shared__ float sred[8];
    int t = threadIdx.x;
    int warp = t >> 5, lane = t & 31;
    float4 qv = ((const float4*)q)[t];
    ((float4*)sq)[t] = qv;
    float p = qv.x*qv.x + qv.y*qv.y + qv.z*qv.z + qv.w*qv.w;
    #pragma unroll
    for (int o = 16; o > 0; o >>= 1) p += __shfl_xor_sync(0xffffffffu, p, o);
    if (lane == 0) sred[warp] = p;
    __syncthreads();
    float qn = sqrtf(sred[0]+sred[1]+sred[2]+sred[3]+sred[4]+sred[5]+sred[6]+sred[7]);

    int rbase = blockIdx.x * 64 + warp * 8;
    for (int rr = 0; rr < 8; rr += 2) {
        int r0 = rbase + rr;
        const float4* row0 = (const float4*)(mem + (size_t)r0 * D_MODEL);
        const float4* row1 = (const float4*)(mem + (size_t)(r0+1) * D_MODEL);
        float d0 = 0.f, n0 = 0.f, d1 = 0.f, n1 = 0.f;
        #pragma unroll
        for (int i = 0; i < 8; i++) {
            int j = i * 32 + lane;
            float4 m0 = row0[j];
            float4 m1 = row1[j];
            float4 s = *(const float4*)&sq[j*4];
            d0 += m0.x*s.x + m0.y*s.y + m0.z*s.z + m0.w*s.w;
            n0 += m0.x*m0.x + m0.y*m0.y + m0.z*m0.z + m0.w*m0.w;
            d1 += m1.x*s.x + m1.y*s.y + m1.z*s.z + m1.w*s.w;
            n1 += m1.x*m1.x + m1.y*m1.y + m1.z*m1.z + m1.w*m1.w;
        }
        #pragma unroll
        for (int o = 16; o > 0; o >>= 1) {
            d0 += __shfl_xor_sync(0xffffffffu, d0, o);
            n0 += __shfl_xor_sync(0xffffffffu, n0, o);
            d1 += __shfl_xor_sync(0xffffffffu, d1, o);
            n1 += __shfl_xor_sync(0xffffffffu, n1, o);
        }
        if (lane == 0) {
            float s0 = d0 / fmaxf(sqrtf(n0) * qn, EPS_COS);
            float s1 = d1 / fmaxf(sqrtf(n1) * qn, EPS_COS);
            g_sims[r0]   = s0;
            g_sims[r0+1] = s1;
            atomicAdd(&g_hist16[fkey(s0) >> 16], 1u);
            atomicAdd(&g_hist16[fkey(s1) >> 16], 1u);
        }
    }
}

// ---------------- K2: select ----------------
__global__ void __launch_bounds__(NTHR)
k_select(const int* __restrict__ usage, float* __restrict__ outU, int hasU)
{
    __shared__ unsigned int sc4[4];
    __shared__ unsigned int sco[512], ssuf[512];
    __shared__ unsigned int sfine[128];
    __shared__ int sseg;
    __shared__ unsigned int sabove;
    __shared__ float sv[CAND_CAP];
    __shared__ int   si[CAND_CAP];
    int t = threadIdx.x, bid = blockIdx.x;

    if (bid < 128) {
        if (t < 4) sc4[t] = 0u;
        __syncthreads();
        unsigned int v = g_hist16[bid * 512 + t];
        if (v) atomicAdd(&sc4[t >> 7], v);
        __syncthreads();
        if (t < 4) g_coarse[bid * 4 + t] = sc4[t];
    }
    gbar();

    if (bid == 0) {
        sco[t] = g_coarse[t];
        ssuf[t] = sco[t];
        __syncthreads();
        for (int off = 1; off < 512; off <<= 1) {
            unsigned int v = (t + off < 512) ? ssuf[t + off] : 0u;
            __syncthreads();
            ssuf[t] += v;
            __syncthreads();
        }
        unsigned int above = ssuf[t] - sco[t];
        if (above < TOP_K && ssuf[t] >= TOP_K) { sseg = t; sabove = above; }
        __syncthreads();
        if (t < 128) sfine[t] = g_hist16[sseg * 128 + t];
        __syncthreads();
        if (t == 0) {
            unsigned int cum = sabove;
            int pivot = sseg * 128;
            for (int b = 127; b >= 0; b--) {
                cum += sfine[b];
                if (cum >= TOP_K) { pivot = sseg * 128 + b; break; }
            }
            g_p16 = pivot;
            g_ccnt = 0u;
        }
    }
    gbar();

    {
        int i4 = bid * NTHR + t;
        if (i4 < MEM_SIZE/4) {
            int p16 = g_p16;
            float4 v4 = ((const float4*)g_sims)[i4];
            int base = i4 * 4;
            float vv[4] = {v4.x, v4.y, v4.z, v4.w};
            #pragma unroll
            for (int j = 0; j < 4; j++) {
                if ((int)(fkey(vv[j]) >> 16) >= p16) {
                    unsigned int p = atomicAdd(&g_ccnt, 1u);
                    if (p < CAND_CAP) { g_cval[p] = vv[j]; g_cidx[p] = base + j; }
                }
            }
            if (hasU) {
                int4 u4 = ((const int4*)usage)[i4];
                ((float4*)outU)[i4] = make_float4((float)u4.x, (float)u4.y, (float)u4.z, (float)u4.w);
            }
            g_hist16[2*i4]   = 0u;
            g_hist16[2*i4+1] = 0u;
        }
    }
    gbar();

    if (bid == 0) {
        int C = (int)min(g_ccnt, (unsigned int)CAND_CAP);
        for (int i = t; i < C; i += NTHR) { sv[i] = g_cval[i]; si[i] = g_cidx[i]; }
        __syncthreads();
        for (int i = t; i < C; i += NTHR) {
            float v = sv[i]; int id = si[i];
            int rank = 0;
            for (int j = 0; j < C; j++)
                rank += before_pair(sv[j], si[j], v, id) ? 1 : 0;
            if (rank < TOP_K) {
                g_topk[rank] = id;
                if (hasU) outU[id] = (float)(usage[id] + 1);
            }
        }
    }
}

// ---------------- K3: merged tail: gemm -> xdbl -> delta+scan -> outproj -> ln ----
#define KTILE 64
#define XSTR  17   // quads per row: odd stride

union SmemT {
    struct { float4 xs4[64 * XSTR]; float4 ws4[16 * XSTR]; float uo[64][17]; } gm;
    struct { float su[4][D_INNER]; } xd;
    struct { float sdt[64][64]; float sB[L_SEQ][D_STATE];
             float sC[D_STATE]; float sdelta[64][16];
             float sus[64][16]; } sc;
    struct { float sy[D_INNER]; float sp[16]; } op;
    struct { float red[NTHR]; } ln;
};

__global__ void __launch_bounds__(NTHR)
k_tail(const float* __restrict__ mem, const float* __restrict__ W,
       const float* __restrict__ cw,  const float* __restrict__ cb,
       const float* __restrict__ Wx,
       const float* __restrict__ Wd,  const float* __restrict__ bd,
       const float* __restrict__ Alog, const float* __restrict__ Dp,
       const float* __restrict__ Wo,
       const float* __restrict__ lng, const float* __restrict__ lnb,
       float* __restrict__ outF)
{
    __shared__ SmemT sm;
    __shared__ int sidx[64];
    int t = threadIdx.x, bid = blockIdx.x;
    int warp = t >> 5, lane = t & 31;

    // ---- PG: u-GEMM (blocks 0..127, 64x16 tile, 2 outputs/thread) ; z63 (128..147) ----
    if (bid < 128) {
        if (t < 64) sidx[t] = g_topk[t];
        __syncthreads();
        int cbase = bid * 16;
        int tr = t & 15;                 // broadcast-friendly row index
        int col = (t >> 4) & 15;         // 16 cols
        int rgrp = t >> 8;               // 0/1
        int r0 = tr + 32 * rgrp;         // rows r0, r0+16
        float acc0 = 0.f, acc1 = 0.f;

        float4 px[2], pw0;
        // preload tile 0: x 1024 quads (2/thread), w 256 quads (threads 0..255)
        #pragma unroll
        for (int j = 0; j < 2; j++) {
            int qi = t + j * NTHR;
            px[j] = *(const float4*)&mem[(size_t)sidx[qi >> 4] * D_MODEL + (qi & 15) * 4];
        }
        if (t < 256)
            pw0 = *(const float4*)&W[(size_t)(cbase + (t >> 4)) * D_MODEL + (t & 15) * 4];
        #pragma unroll
        for (int j = 0; j < 2; j++) { int qi = t + j*NTHR; sm.gm.xs4[(qi >> 4) * XSTR + (qi & 15)] = px[j]; }
        if (t < 256) sm.gm.ws4[(t >> 4) * XSTR + (t & 15)] = pw0;
        __syncthreads();

        for (int kt = 0; kt < D_MODEL; kt += KTILE) {
            bool has_next = (kt + KTILE) < D_MODEL;
            if (has_next) {
                int kn = kt + KTILE;
                #pragma unroll
                for (int j = 0; j < 2; j++) {
                    int qi = t + j * NTHR;
                    px[j] = *(const float4*)&mem[(size_t)sidx[qi >> 4] * D_MODEL + kn + (qi & 15) * 4];
                }
                if (t < 256)
                    pw0 = *(const float4*)&W[(size_t)(cbase + (t >> 4)) * D_MODEL + kn + (t & 15) * 4];
            }
            #pragma unroll
            for (int p = 0; p < 16; p++) {
                float4 w = sm.gm.ws4[col * XSTR + p];
                float4 xa = sm.gm.xs4[r0 * XSTR + p];
                float4 xb = sm.gm.xs4[(r0 + 16) * XSTR + p];
                acc0 += xa.x*w.x + xa.y*w.y + xa.z*w.z + xa.w*w.w;
                acc1 += xb.x*w.x + xb.y*w.y + xb.z*w.z + xb.w*w.w;
            }
            __syncthreads();
            if (has_next) {
                #pragma unroll
                for (int j = 0; j < 2; j++) { int qi = t + j*NTHR; sm.gm.xs4[(qi >> 4) * XSTR + (qi & 15)] = px[j]; }
                if (t < 256) sm.gm.ws4[(t >> 4) * XSTR + (t & 15)] = pw0;
            }
            __syncthreads();
        }

        sm.gm.uo[r0][col]      = acc0;
        sm.gm.uo[r0 + 16][col] = acc1;
        __syncthreads();
        // conv + silu (each thread: its 2 rows, same col)
        int e = cbase + col;
        float4 w4 = *(const float4*)&cw[e * D_CONV];
        float bias = cb[e];
        float u0, u1;
        {
            int l = r0;
            float s = bias + sm.gm.uo[l][col] * w4.w;
            if (l >= 1) s += sm.gm.uo[l-1][col] * w4.z;
            if (l >= 2) s += sm.gm.uo[l-2][col] * w4.y;
            if (l >= 3) s += sm.gm.uo[l-3][col] * w4.x;
            u0 = s / (1.f + expf(-s));
        }
        {
            int l = r0 + 16;
            float s = bias + sm.gm.uo[l][col] * w4.w;
            s += sm.gm.uo[l-1][col] * w4.z;
            s += sm.gm.uo[l-2][col] * w4.y;
            s += sm.gm.uo[l-3][col] * w4.x;
            u1 = s / (1.f + expf(-s));
        }
        __syncthreads();
        sm.gm.uo[r0][col]      = u0;
        sm.gm.uo[r0 + 16][col] = u1;
        __syncthreads();
        #pragma unroll
        for (int j = 0; j < 2; j++) {
            int idx = t + j * NTHR;          // 0..1023
            int l = idx >> 4, c = idx & 15;
            g_uact[l * D_INNER + cbase + c] = sm.gm.uo[l][c];
        }
    } else {
        // z63 matvec: blocks 128..147 -> 320 warps over 2048 outputs
        int i63 = g_topk[TOP_K-1];
        const float4* x63 = (const float4*)(mem + (size_t)i63 * D_MODEL);
        int wg = (bid - 128) * 16 + warp;      // 0..319
        for (int e = wg; e < D_INNER; e += 320) {
            const float4* wr = (const float4*)(W + (size_t)(D_INNER + e) * D_MODEL);
            float a = 0.f;
            #pragma unroll
            for (int i = 0; i < 8; i++) {
                int j = i * 32 + lane;
                float4 w = wr[j];
                float4 x = x63[j];
                a += w.x*x.x + w.y*x.y + w.z*x.z + w.w*x.w;
            }
            #pragma unroll
            for (int off = 16; off > 0; off >>= 1) a += __shfl_xor_sync(0xffffffffu, a, off);
            if (lane == 0) g_z63[e] = a;
        }
    }
    gbar();

    // ---- P4: x_proj GEMV (blocks 0..95); blocks 96..147 prefetch Wo into L2 ----
    if (bid < 96) {
        int ochunk = bid % 6, lchunk = bid / 6;
        int lbase = lchunk * 4;
        for (int i = t; i < 4 * D_INNER / 4; i += NTHR)
            ((float4*)&sm.xd.su[0][0])[i] = ((const float4*)(g_uact + (size_t)lbase * D_INNER))[i];
        __syncthreads();
        int o = ochunk * 16 + warp;
        const float4* wr = (const float4*)(Wx + (size_t)o * D_INNER);
        float a0 = 0.f, a1 = 0.f, a2 = 0.f, a3 = 0.f;
        #pragma unroll 4
        for (int i = lane; i < D_INNER/4; i += 32) {
            float4 w  = wr[i];
            float4 s0 = ((const float4*)sm.xd.su[0])[i];
            float4 s1 = ((const float4*)sm.xd.su[1])[i];
            float4 s2 = ((const float4*)sm.xd.su[2])[i];
            float4 s3 = ((const float4*)sm.xd.su[3])[i];
            a0 += w.x*s0.x + w.y*s0.y + w.z*s0.z + w.w*s0.w;
            a1 += w.x*s1.x + w.y*s1.y + w.z*s1.z + w.w*s1.w;
            a2 += w.x*s2.x + w.y*s2.y + w.z*s2.z + w.w*s2.w;
            a3 += w.x*s3.x + w.y*s3.y + w.z*s3.z + w.w*s3.w;
        }
        #pragma unroll
        for (int off = 16; off > 0; off >>= 1) {
            a0 += __shfl_xor_sync(0xffffffffu, a0, off);
            a1 += __shfl_xor_sync(0xffffffffu, a1, off);
            a2 += __shfl_xor_sync(0xffffffffu, a2, off);
            a3 += __shfl_xor_sync(0xffffffffu, a3, off);
        }
        if (lane == 0) {
            g_xdbl[(lbase+0) * XPROJ_OUT + o] = a0;
            g_xdbl[(lbase+1) * XPROJ_OUT + o] = a1;
            g_xdbl[(lbase+2) * XPROJ_OUT + o] = a2;
            g_xdbl[(lbase+3) * XPROJ_OUT + o] = a3;
        }
    } else {
        const float4* wo4 = (const float4*)Wo;
        const int n4 = D_MODEL * D_INNER / 4;
        float s = 0.f;
        for (int i = (bid - 96) * NTHR + t; i < n4; i += 52 * NTHR) {
            float4 v = wo4[i];
            s += v.x + v.y + v.z + v.w;
        }
        g_sink[bid] = s;
    }
    gbar();

    // ---- P5+P6: delta + scan (128 blocks, 16 d's each) ----
    if (bid < 128) {
        int dbase = bid * 16;
        for (int i = t; i < 4096; i += NTHR) {
            int l = i >> 6, r = i & 63;
            sm.sc.sdt[l][r] = g_xdbl[l * XPROJ_OUT + r];
        }
        for (int i = t; i < L_SEQ * D_STATE; i += NTHR) {
            int l = i >> 4, s = i & 15;
            sm.sc.sB[l][s] = g_xdbl[l * XPROJ_OUT + DT_RANK + s];
        }
        if (t < D_STATE)
            sm.sc.sC[t] = g_xdbl[(L_SEQ-1) * XPROJ_OUT + DT_RANK + D_STATE + t];
        __syncthreads();
        for (int i = t; i < 1024; i += NTHR) {
            int dl = i & 15, l = i >> 4;
            int d = dbase + dl;
            float acc = bd[d];
            const float4* wr = (const float4*)(Wd + (size_t)d * DT_RANK);
            const float* sl = sm.sc.sdt[l];
            #pragma unroll
            for (int r = 0; r < DT_RANK/4; r++) {
                float4 w = wr[r];
                acc += sl[r*4]*w.x + sl[r*4+1]*w.y + sl[r*4+2]*w.z + sl[r*4+3]*w.w;
            }
            sm.sc.sdelta[l][dl] = (acc > 25.f) ? acc : log1pf(expf(acc));
            sm.sc.sus[l][dl] = g_uact[l * D_INNER + d];
        }
        __syncthreads();
        if (t < 256) {
            int dl = t >> 4, s = t & 15;
            int d = dbase + dl;
            float As = -expf(Alog[d * D_STATE + s]);
            float A0 = __shfl_sync(0xffffffffu, As, lane & 0x10, 32);
            bool fast = fabsf(As - A0 * (float)(s+1)) <= 1e-5f * (float)(s+1) * fabsf(A0);
            bool allfast = __all_sync(0xffffffffu, fast);
            float h = 0.f;
            if (allfast) {
                int n = s + 1;
                #pragma unroll 4
                for (int l = 0; l < L_SEQ; l++) {
                    float dv = sm.sc.sdelta[l][dl];
                    float uv = sm.sc.sus[l][dl];
                    float e1 = 0.f;
                    if (s == 0) e1 = __expf(dv * A0);
                    e1 = __shfl_sync(0xffffffffu, e1, lane & 0x10, 32);
                    float e2 = e1*e1, e4 = e2*e2, e8 = e4*e4, e16 = e8*e8;
                    float ep = 1.f;
                    if (n & 1)  ep *= e1;
                    if (n & 2)  ep *= e2;
                    if (n & 4)  ep *= e4;
                    if (n & 8)  ep *= e8;
                    if (n & 16) ep *= e16;
                    h = ep * h + dv * uv * sm.sc.sB[l][s];
                }
            } else {
                for (int l = 0; l < L_SEQ; l++) {
                    float dv = sm.sc.sdelta[l][dl];
                    float uv = sm.sc.sus[l][dl];
                    h = __expf(dv * As) * h + dv * uv * sm.sc.sB[l][s];
                }
            }
            float partial = h * sm.sc.sC[s];
            #pragma unroll
            for (int off = 8; off > 0; off >>= 1)
                partial += __shfl_xor_sync(0xffffffffu, partial, off);
            if (s == 0) {
                float uv63 = sm.sc.sus[L_SEQ-1][dl];
                float zv = g_z63[d];
                float sz = zv / (1.f + expf(-zv));
                g_y[d] = (partial + uv63 * Dp[d]) * sz;
            }
        }
    }
    gbar();

    // ---- P7: out_proj — 128 blocks, 2 warps per output ----
    if (bid < 128) {
        for (int i = t; i < D_INNER; i += NTHR) sm.op.sy[i] = g_y[i];
        __syncthreads();
        int e = bid * 8 + (warp >> 1);
        int half = warp & 1;
        const float4* wr  = (const float4*)(Wo + (size_t)e * D_INNER) + half * 256;
        const float4* syp = ((const float4*)sm.op.sy) + half * 256;
        float a = 0.f;
        #pragma unroll
        for (int i = 0; i < 8; i++) {
            int j = i * 32 + lane;
            float4 w = wr[j];
            float4 s = syp[j];
            a += w.x*s.x + w.y*s.y + w.z*s.z + w.w*s.w;
        }
        #pragma unroll
        for (int off = 16; off > 0; off >>= 1) a += __shfl_xor_sync(0xffffffffu, a, off);
        if (lane == 0) sm.op.sp[warp] = a;
        __syncthreads();
        if (t < 8) g_ctx[bid * 8 + t] = sm.op.sp[2*t] + sm.op.sp[2*t + 1];
    }
    gbar();

    // ---- P8: layernorm (block 0) ----
    if (bid == 0) {
        float v0 = g_ctx[t], v1 = g_ctx[t + NTHR];
        sm.ln.red[t] = v0 + v1; __syncthreads();
        for (int o = 256; o > 0; o >>= 1) { if (t < o) sm.ln.red[t] += sm.ln.red[t+o]; __syncthreads(); }
        float mu = sm.ln.red[0] / (float)D_MODEL;
        __syncthreads();
        float d0 = v0 - mu, d1 = v1 - mu;
        sm.ln.red[t] = d0*d0 + d1*d1; __syncthreads();
        for (int o = 256; o > 0; o >>= 1) { if (t < o) sm.ln.red[t] += sm.ln.red[t+o]; __syncthreads(); }
        float rs = rsqrtf(sm.ln.red[0] / (float)D_MODEL + EPS_LN);
        outF[t]        = d0 * rs * lng[t]        + lnb[t];
        outF[t + NTHR] = d1 * rs * lng[t + NTHR] + lnb[t + NTHR];
    }
}

// ---------------- launch ----------------
extern "C" void kernel_launch(void* const* d_in, const int* in_sizes, int n_in,
                              void* d_out, int out_size) {
    const float* query    = (const float*)d_in[0];
    const float* memory   = (const float*)d_in[1];
    const int*   usage    = (const int*)  d_in[2];
    const float* in_proj  = (const float*)d_in[3];
    const float* conv_w   = (const float*)d_in[4];
    const float* conv_b   = (const float*)d_in[5];
    const float* x_proj   = (const float*)d_in[6];
    const float* dt_proj  = (const float*)d_in[7];
    const float* dt_b     = (const float*)d_in[8];
    const float* A_log    = (const float*)d_in[9];
    const float* Dp       = (const float*)d_in[10];
    const float* out_proj = (const float*)d_in[11];
    const float* ln_g     = (const float*)d_in[12];
    const float* ln_b     = (const float*)d_in[13];

    float* outF = (float*)d_out;
    bool has_usage = (out_size >= D_MODEL + MEM_SIZE);
    float* outU = outF + D_MODEL;
    int hasU = has_usage ? 1 : 0;
    float* outUp = has_usage ? outU : (float*)nullptr;

    k_sims<<<MEM_SIZE/64, 256>>>(memory, query);                  // #1
    k_select<<<NBLK, NTHR>>>(usage, outUp, hasU);                 // #2
    k_tail<<<NBLK, NTHR>>>(memory, in_proj, conv_w, conv_b,       // #3
                           x_proj, dt_proj, dt_b, A_log, Dp,
                           out_proj, ln_g, ln_b, outF);
}

// round 16
// speedup vs baseline: 1.0662x; 1.0662x over previous
#include <cuda_runtime.h>
#include <cuda_bf16.h>
#include <math.h>

#define D_MODEL   1024
#define MEM_SIZE  131072
#define TOP_K     64
#define D_STATE   16
#define D_CONV    4
#define D_INNER   2048
#define DT_RANK   64
#define XPROJ_OUT (DT_RANK + 2*D_STATE)   // 96
#define L_SEQ     64
#define EPS_COS   1e-8f
#define EPS_LN    1e-5f
#define CAND_CAP  2048
#define NBLK      148
#define NTHR      512
#define GTHR      128

// ---------------- scratch ----------------
__device__ float g_sims[MEM_SIZE];
__device__ unsigned int g_hist16[65536];
__device__ unsigned int g_coarse[512];
__device__ int g_p16;
__device__ unsigned int g_ccnt;
__device__ float g_cval[CAND_CAP];
__device__ int   g_cidx[CAND_CAP];
__device__ int   g_topk[TOP_K];
__device__ float g_uact[L_SEQ * D_INNER];
__device__ float g_z63[D_INNER];
__device__ float g_xdbl[L_SEQ * XPROJ_OUT];
__device__ float g_y[D_INNER];
__device__ float g_ctx[D_MODEL];
__device__ float g_sink[NBLK];
__device__ unsigned int g_bar_count;
__device__ unsigned int g_bar_gen;

__device__ __forceinline__ unsigned int fkey(float v) {
    unsigned int u = __float_as_uint(v);
    return (u & 0x80000000u) ? ~u : (u | 0x80000000u);
}
__device__ __forceinline__ bool before_pair(float va, int ia, float vb, int ib) {
    return (va > vb) || (va == vb && ia < ib);
}

__device__ __forceinline__ void gbar() {
    __syncthreads();
    __threadfence();
    if (threadIdx.x == 0) {
        volatile unsigned int* genp = &g_bar_gen;
        unsigned int gen = *genp;
        if (atomicAdd(&g_bar_count, 1u) == gridDim.x - 1) {
            g_bar_count = 0u;
            __threadfence();
            *genp = gen + 1u;
        } else {
            while (*genp == gen) { }
        }
    }
    __syncthreads();
}

// ---------------- K1: qnorm + cosine sims + hist16 + usage copy ----------------
__global__ void k_sims(const float* __restrict__ mem, const float* __restrict__ q,
                       const int* __restrict__ usage, float* __restrict__ outU, int hasU) {
    __shared__ __align__(16) float sq[D_MODEL];
    __shared__ float sred[8];
    int t = threadIdx.x;
    int warp = t >> 5, lane = t & 31;
    float4 qv = ((const float4*)q)[t];
    ((float4*)sq)[t] = qv;
    float p = qv.x*qv.x + qv.y*qv.y + qv.z*qv.z + qv.w*qv.w;
    #pragma unroll
    for (int o = 16; o > 0; o >>= 1) p += __shfl_xor_sync(0xffffffffu, p, o);
    if (lane == 0) sred[warp] = p;
    __syncthreads();
    float qn = sqrtf(sred[0]+sred[1]+sred[2]+sred[3]+sred[4]+sred[5]+sred[6]+sred[7]);

    // usage copy for this block's 64 rows (independent of sims math)
    if (hasU && t < 16) {
        int i4 = blockIdx.x * 16 + t;
        int4 u4 = ((const int4*)usage)[i4];
        ((float4*)outU)[i4] = make_float4((float)u4.x, (float)u4.y, (float)u4.z, (float)u4.w);
    }

    int rbase = blockIdx.x * 64 + warp * 8;
    for (int rr = 0; rr < 8; rr += 2) {
        int r0 = rbase + rr;
        const float4* row0 = (const float4*)(mem + (size_t)r0 * D_MODEL);
        const float4* row1 = (const float4*)(mem + (size_t)(r0+1) * D_MODEL);
        float d0 = 0.f, n0 = 0.f, d1 = 0.f, n1 = 0.f;
        #pragma unroll
        for (int i = 0; i < 8; i++) {
            int j = i * 32 + lane;
            float4 m0 = row0[j];
            float4 m1 = row1[j];
            float4 s = *(const float4*)&sq[j*4];
            d0 += m0.x*s.x + m0.y*s.y + m0.z*s.z + m0.w*s.w;
            n0 += m0.x*m0.x + m0.y*m0.y + m0.z*m0.z + m0.w*m0.w;
            d1 += m1.x*s.x + m1.y*s.y + m1.z*s.z + m1.w*s.w;
            n1 += m1.x*m1.x + m1.y*m1.y + m1.z*m1.z + m1.w*m1.w;
        }
        #pragma unroll
        for (int o = 16; o > 0; o >>= 1) {
            d0 += __shfl_xor_sync(0xffffffffu, d0, o);
            n0 += __shfl_xor_sync(0xffffffffu, n0, o);
            d1 += __shfl_xor_sync(0xffffffffu, d1, o);
            n1 += __shfl_xor_sync(0xffffffffu, n1, o);
        }
        if (lane == 0) {
            float s0 = d0 / fmaxf(sqrtf(n0) * qn, EPS_COS);
            float s1 = d1 / fmaxf(sqrtf(n1) * qn, EPS_COS);
            g_sims[r0]   = s0;
            g_sims[r0+1] = s1;
            atomicAdd(&g_hist16[fkey(s0) >> 16], 1u);
            atomicAdd(&g_hist16[fkey(s1) >> 16], 1u);
        }
    }
}

// ---------------- K2: select (128 thr) + u-GEMM + z63 ----------------
#define KTILE 64
#define XSTR  17

union SmemM {
    struct { unsigned int ssuf[GTHR]; unsigned int sfine[128]; } pv;
    struct { float sv[CAND_CAP]; int si[CAND_CAP]; } fin;
    struct { float4 xs4[64 * XSTR]; float4 ws4[16 * XSTR]; float uo[64][17]; } gm;
};

__global__ void __launch_bounds__(GTHR)
k_mid(const float* __restrict__ mem, const float* __restrict__ W,
      const float* __restrict__ cw,  const float* __restrict__ cb,
      const int* __restrict__ usage, float* __restrict__ outU, int hasU)
{
    __shared__ SmemM sm;
    __shared__ int sseg;
    __shared__ unsigned int sabove;
    __shared__ int sidx[64];
    int t = threadIdx.x, bid = blockIdx.x;
    int warp = t >> 5, lane = t & 31;

    // ---- PB: coarse sums (blocks 0..127): 512 fine bins -> 4 coarse ----
    if (bid < 128) {
        #pragma unroll
        for (int j = 0; j < 4; j++) {
            unsigned int v = g_hist16[bid * 512 + j * 128 + t];
            #pragma unroll
            for (int o = 16; o > 0; o >>= 1) v += __shfl_xor_sync(0xffffffffu, v, o);
            if (lane == 0) atomicAdd(&g_coarse[bid * 4 + j], v);
        }
    }
    gbar();

    // ---- PC: pivot (block 0, 128 threads each owning 4 coarse bins) ----
    if (bid == 0) {
        unsigned int cc[4];
        #pragma unroll
        for (int b = 0; b < 4; b++) cc[b] = g_coarse[4*t + b];
        unsigned int lsum = cc[0] + cc[1] + cc[2] + cc[3];
        sm.pv.ssuf[t] = lsum;
        __syncthreads();
        for (int off = 1; off < GTHR; off <<= 1) {
            unsigned int v = (t + off < GTHR) ? sm.pv.ssuf[t + off] : 0u;
            __syncthreads();
            sm.pv.ssuf[t] += v;
            __syncthreads();
        }
        unsigned int cum = sm.pv.ssuf[t] - lsum;   // above coarse bins >= 4t+4
        #pragma unroll
        for (int b = 3; b >= 0; b--) {
            unsigned int above_b = cum;
            cum += cc[b];
            if (above_b < TOP_K && cum >= TOP_K) { sseg = 4*t + b; sabove = above_b; }
        }
        __syncthreads();
        sm.pv.sfine[t] = g_hist16[sseg * 128 + t];
        __syncthreads();
        if (t == 0) {
            unsigned int cum2 = sabove;
            int pivot = sseg * 128;
            for (int b = 127; b >= 0; b--) {
                cum2 += sm.pv.sfine[b];
                if (cum2 >= TOP_K) { pivot = sseg * 128 + b; break; }
            }
            g_p16 = pivot;
            g_ccnt = 0u;
        }
    }
    gbar();

    // ---- PD: collect + hist/coarse rezero ----
    {
        int p16 = g_p16;
        for (int i4 = bid * GTHR + t; i4 < MEM_SIZE/4; i4 += NBLK * GTHR) {
            float4 v4 = ((const float4*)g_sims)[i4];
            int base = i4 * 4;
            float vv[4] = {v4.x, v4.y, v4.z, v4.w};
            #pragma unroll
            for (int j = 0; j < 4; j++) {
                if ((int)(fkey(vv[j]) >> 16) >= p16) {
                    unsigned int p = atomicAdd(&g_ccnt, 1u);
                    if (p < CAND_CAP) { g_cval[p] = vv[j]; g_cidx[p] = base + j; }
                }
            }
        }
        for (int i = bid * GTHR + t; i < 16384; i += NBLK * GTHR)
            ((uint4*)g_hist16)[i] = make_uint4(0u, 0u, 0u, 0u);
        if (bid == 0 && t < 128) {
            g_coarse[4*t] = 0u; g_coarse[4*t+1] = 0u;
            g_coarse[4*t+2] = 0u; g_coarse[4*t+3] = 0u;
        }
    }
    gbar();

    // ---- PE: rank (block 0) + usage scatter ----
    if (bid == 0) {
        int C = (int)min(g_ccnt, (unsigned int)CAND_CAP);
        for (int i = t; i < C; i += GTHR) { sm.fin.sv[i] = g_cval[i]; sm.fin.si[i] = g_cidx[i]; }
        __syncthreads();
        for (int i = t; i < C; i += GTHR) {
            float v = sm.fin.sv[i]; int id = sm.fin.si[i];
            int rank = 0;
            for (int j = 0; j < C; j++)
                rank += before_pair(sm.fin.sv[j], sm.fin.si[j], v, id) ? 1 : 0;
            if (rank < TOP_K) {
                g_topk[rank] = id;
                if (hasU) outU[id] = (float)(usage[id] + 1);
            }
        }
    }
    gbar();

    // ---- PG: u-GEMM (blocks 0..127, R14 tiling) ; z63 matvec (128..147) ----
    if (bid < 128) {
        if (t < 64) sidx[t] = g_topk[t];
        __syncthreads();
        int cbase = bid * 16;
        int tr = t & 15, tc = t >> 4;
        float acc[4][2] = {{0.f,0.f},{0.f,0.f},{0.f,0.f},{0.f,0.f}};

        float4 px[8], pw[2];
        #pragma unroll
        for (int j = 0; j < 8; j++) {
            int qi = t + j * GTHR;
            px[j] = *(const float4*)&mem[(size_t)sidx[qi >> 4] * D_MODEL + (qi & 15) * 4];
        }
        #pragma unroll
        for (int j = 0; j < 2; j++) {
            int qi = t + j * GTHR;
            pw[j] = *(const float4*)&W[(size_t)(cbase + (qi >> 4)) * D_MODEL + (qi & 15) * 4];
        }
        #pragma unroll
        for (int j = 0; j < 8; j++) { int qi = t + j*GTHR; sm.gm.xs4[(qi >> 4) * XSTR + (qi & 15)] = px[j]; }
        #pragma unroll
        for (int j = 0; j < 2; j++) { int qi = t + j*GTHR; sm.gm.ws4[(qi >> 4) * XSTR + (qi & 15)] = pw[j]; }
        __syncthreads();

        for (int kt = 0; kt < D_MODEL; kt += KTILE) {
            bool has_next = (kt + KTILE) < D_MODEL;
            if (has_next) {
                int kn = kt + KTILE;
                #pragma unroll
                for (int j = 0; j < 8; j++) {
                    int qi = t + j * GTHR;
                    px[j] = *(const float4*)&mem[(size_t)sidx[qi >> 4] * D_MODEL + kn + (qi & 15) * 4];
                }
                #pragma unroll
                for (int j = 0; j < 2; j++) {
                    int qi = t + j * GTHR;
                    pw[j] = *(const float4*)&W[(size_t)(cbase + (qi >> 4)) * D_MODEL + kn + (qi & 15) * 4];
                }
            }
            #pragma unroll
            for (int p = 0; p < 16; p++) {
                float4 w0 = sm.gm.ws4[(tc * 2)     * XSTR + p];
                float4 w1 = sm.gm.ws4[(tc * 2 + 1) * XSTR + p];
                #pragma unroll
                for (int i = 0; i < 4; i++) {
                    float4 x = sm.gm.xs4[(tr + 16 * i) * XSTR + p];
                    acc[i][0] += x.x*w0.x + x.y*w0.y + x.z*w0.z + x.w*w0.w;
                    acc[i][1] += x.x*w1.x + x.y*w1.y + x.z*w1.z + x.w*w1.w;
                }
            }
            __syncthreads();
            if (has_next) {
                #pragma unroll
                for (int j = 0; j < 8; j++) { int qi = t + j*GTHR; sm.gm.xs4[(qi >> 4) * XSTR + (qi & 15)] = px[j]; }
                #pragma unroll
                for (int j = 0; j < 2; j++) { int qi = t + j*GTHR; sm.gm.ws4[(qi >> 4) * XSTR + (qi & 15)] = pw[j]; }
            }
            __syncthreads();
        }

        #pragma unroll
        for (int i = 0; i < 4; i++) {
            sm.gm.uo[tr + 16*i][tc*2]     = acc[i][0];
            sm.gm.uo[tr + 16*i][tc*2 + 1] = acc[i][1];
        }
        __syncthreads();
        float ures[4][2];
        #pragma unroll
        for (int c = 0; c < 2; c++) {
            int cc = tc*2 + c;
            int e = cbase + cc;
            float4 w4 = *(const float4*)&cw[e * D_CONV];
            float bias = cb[e];
            #pragma unroll
            for (int i = 0; i < 4; i++) {
                int l = tr + 16*i;
                float s = bias + sm.gm.uo[l][cc] * w4.w;
                if (l >= 1) s += sm.gm.uo[l-1][cc] * w4.z;
                if (l >= 2) s += sm.gm.uo[l-2][cc] * w4.y;
                if (l >= 3) s += sm.gm.uo[l-3][cc] * w4.x;
                ures[i][c] = s / (1.f + expf(-s));
            }
        }
        __syncthreads();
        #pragma unroll
        for (int i = 0; i < 4; i++) {
            sm.gm.uo[tr + 16*i][tc*2]     = ures[i][0];
            sm.gm.uo[tr + 16*i][tc*2 + 1] = ures[i][1];
        }
        __syncthreads();
        #pragma unroll
        for (int j = 0; j < 8; j++) {
            int idx = t + j * GTHR;
            int l = idx >> 4, c = idx & 15;
            g_uact[l * D_INNER + cbase + c] = sm.gm.uo[l][c];
        }
    } else {
        int i63 = g_topk[TOP_K-1];
        const float4* x63 = (const float4*)(mem + (size_t)i63 * D_MODEL);
        int wg = (bid - 128) * 4 + warp;
        for (int base = 0; base < 7; base++) {
            int e0 = wg + (base*4) * 80;
            float a0 = 0.f, a1 = 0.f, a2 = 0.f, a3 = 0.f;
            const float4* w0 = (const float4*)(W + (size_t)(D_INNER + ((e0       < D_INNER) ? e0       : 0)) * D_MODEL);
            const float4* w1 = (const float4*)(W + (size_t)(D_INNER + ((e0 + 80  < D_INNER) ? e0 + 80  : 0)) * D_MODEL);
            const float4* w2 = (const float4*)(W + (size_t)(D_INNER + ((e0 + 160 < D_INNER) ? e0 + 160 : 0)) * D_MODEL);
            const float4* w3 = (const float4*)(W + (size_t)(D_INNER + ((e0 + 240 < D_INNER) ? e0 + 240 : 0)) * D_MODEL);
            #pragma unroll
            for (int i = 0; i < 8; i++) {
                int j = i * 32 + lane;
                float4 x = x63[j];
                float4 a = w0[j], b = w1[j], c = w2[j], d = w3[j];
                a0 += a.x*x.x + a.y*x.y + a.z*x.z + a.w*x.w;
                a1 += b.x*x.x + b.y*x.y + b.z*x.z + b.w*x.w;
                a2 += c.x*x.x + c.y*x.y + c.z*x.z + c.w*x.w;
                a3 += d.x*x.x + d.y*x.y + d.z*x.z + d.w*x.w;
            }
            #pragma unroll
            for (int off = 16; off > 0; off >>= 1) {
                a0 += __shfl_xor_sync(0xffffffffu, a0, off);
                a1 += __shfl_xor_sync(0xffffffffu, a1, off);
                a2 += __shfl_xor_sync(0xffffffffu, a2, off);
                a3 += __shfl_xor_sync(0xffffffffu, a3, off);
            }
            if (lane == 0) {
                if (e0       < D_INNER) g_z63[e0]       = a0;
                if (e0 + 80  < D_INNER) g_z63[e0 + 80]  = a1;
                if (e0 + 160 < D_INNER) g_z63[e0 + 160] = a2;
                if (e0 + 240 < D_INNER) g_z63[e0 + 240] = a3;
            }
        }
    }
}

// ---------------- K3: xdbl(+Wo prefetch) -> delta+scan -> outproj -> ln --------
union SmemR {
    struct { float su[4][D_INNER]; } xd;
    struct { float sdt[64][64]; float sB[L_SEQ][D_STATE];
             float sC[D_STATE]; float sdelta[64][16];
             float sus[64][16]; } sc;
    struct { float sy[D_INNER]; float sp[16]; } op;
    struct { float red[NTHR]; } ln;
};

__global__ void __launch_bounds__(NTHR)
k_rest(const float* __restrict__ Wx,
       const float* __restrict__ Wd,  const float* __restrict__ bd,
       const float* __restrict__ Alog, const float* __restrict__ Dp,
       const float* __restrict__ Wo,
       const float* __restrict__ lng, const float* __restrict__ lnb,
       float* __restrict__ outF)
{
    __shared__ SmemR sm;
    int t = threadIdx.x, bid = blockIdx.x;
    int warp = t >> 5, lane = t & 31;

    // P4: x_proj GEMV (blocks 0..95); blocks 96..147 prefetch Wo into L2
    if (bid < 96) {
        int ochunk = bid % 6, lchunk = bid / 6;
        int lbase = lchunk * 4;
        for (int i = t; i < 4 * D_INNER / 4; i += NTHR)
            ((float4*)&sm.xd.su[0][0])[i] = ((const float4*)(g_uact + (size_t)lbase * D_INNER))[i];
        __syncthreads();
        int o = ochunk * 16 + warp;
        const float4* wr = (const float4*)(Wx + (size_t)o * D_INNER);
        float a0 = 0.f, a1 = 0.f, a2 = 0.f, a3 = 0.f;
        #pragma unroll 4
        for (int i = lane; i < D_INNER/4; i += 32) {
            float4 w  = wr[i];
            float4 s0 = ((const float4*)sm.xd.su[0])[i];
            float4 s1 = ((const float4*)sm.xd.su[1])[i];
            float4 s2 = ((const float4*)sm.xd.su[2])[i];
            float4 s3 = ((const float4*)sm.xd.su[3])[i];
            a0 += w.x*s0.x + w.y*s0.y + w.z*s0.z + w.w*s0.w;
            a1 += w.x*s1.x + w.y*s1.y + w.z*s1.z + w.w*s1.w;
            a2 += w.x*s2.x + w.y*s2.y + w.z*s2.z + w.w*s2.w;
            a3 += w.x*s3.x + w.y*s3.y + w.z*s3.z + w.w*s3.w;
        }
        #pragma unroll
        for (int off = 16; off > 0; off >>= 1) {
            a0 += __shfl_xor_sync(0xffffffffu, a0, off);
            a1 += __shfl_xor_sync(0xffffffffu, a1, off);
            a2 += __shfl_xor_sync(0xffffffffu, a2, off);
            a3 += __shfl_xor_sync(0xffffffffu, a3, off);
        }
        if (lane == 0) {
            g_xdbl[(lbase+0) * XPROJ_OUT + o] = a0;
            g_xdbl[(lbase+1) * XPROJ_OUT + o] = a1;
            g_xdbl[(lbase+2) * XPROJ_OUT + o] = a2;
            g_xdbl[(lbase+3) * XPROJ_OUT + o] = a3;
        }
    } else {
        const float4* wo4 = (const float4*)Wo;
        const int n4 = D_MODEL * D_INNER / 4;
        float s = 0.f;
        for (int i = (bid - 96) * NTHR + t; i < n4; i += 52 * NTHR) {
            float4 v = wo4[i];
            s += v.x + v.y + v.z + v.w;
        }
        g_sink[bid] = s;
    }
    gbar();

    // P5+P6: delta + scan (128 blocks, 16 d's each)
    if (bid < 128) {
        int dbase = bid * 16;
        for (int i = t; i < 4096; i += NTHR) {
            int l = i >> 6, r = i & 63;
            sm.sc.sdt[l][r] = g_xdbl[l * XPROJ_OUT + r];
        }
        for (int i = t; i < L_SEQ * D_STATE; i += NTHR) {
            int l = i >> 4, s = i & 15;
            sm.sc.sB[l][s] = g_xdbl[l * XPROJ_OUT + DT_RANK + s];
        }
        if (t < D_STATE)
            sm.sc.sC[t] = g_xdbl[(L_SEQ-1) * XPROJ_OUT + DT_RANK + D_STATE + t];
        __syncthreads();
        for (int i = t; i < 1024; i += NTHR) {
            int dl = i & 15, l = i >> 4;
            int d = dbase + dl;
            float acc = bd[d];
            const float4* wr = (const float4*)(Wd + (size_t)d * DT_RANK);
            const float* sl = sm.sc.sdt[l];
            #pragma unroll
            for (int r = 0; r < DT_RANK/4; r++) {
                float4 w = wr[r];
                acc += sl[r*4]*w.x + sl[r*4+1]*w.y + sl[r*4+2]*w.z + sl[r*4+3]*w.w;
            }
            sm.sc.sdelta[l][dl] = (acc > 25.f) ? acc : log1pf(expf(acc));
            sm.sc.sus[l][dl] = g_uact[l * D_INNER + d];
        }
        __syncthreads();
        if (t < 256) {
            int dl = t >> 4, s = t & 15;
            int d = dbase + dl;
            float As = -expf(Alog[d * D_STATE + s]);
            float A0 = __shfl_sync(0xffffffffu, As, lane & 0x10, 32);
            bool fast = fabsf(As - A0 * (float)(s+1)) <= 1e-5f * (float)(s+1) * fabsf(A0);
            bool allfast = __all_sync(0xffffffffu, fast);
            float h = 0.f;
            if (allfast) {
                int n = s + 1;
                #pragma unroll 4
                for (int l = 0; l < L_SEQ; l++) {
                    float dv = sm.sc.sdelta[l][dl];
                    float uv = sm.sc.sus[l][dl];
                    float e1 = 0.f;
                    if (s == 0) e1 = __expf(dv * A0);
                    e1 = __shfl_sync(0xffffffffu, e1, lane & 0x10, 32);
                    float e2 = e1*e1, e4 = e2*e2, e8 = e4*e4, e16 = e8*e8;
                    float ep = 1.f;
                    if (n & 1)  ep *= e1;
                    if (n & 2)  ep *= e2;
                    if (n & 4)  ep *= e4;
                    if (n & 8)  ep *= e8;
                    if (n & 16) ep *= e16;
                    h = ep * h + dv * uv * sm.sc.sB[l][s];
                }
            } else {
                for (int l = 0; l < L_SEQ; l++) {
                    float dv = sm.sc.sdelta[l][dl];
                    float uv = sm.sc.sus[l][dl];
                    h = __expf(dv * As) * h + dv * uv * sm.sc.sB[l][s];
                }
            }
            float partial = h * sm.sc.sC[s];
            #pragma unroll
            for (int off = 8; off > 0; off >>= 1)
                partial += __shfl_xor_sync(0xffffffffu, partial, off);
            if (s == 0) {
                float uv63 = sm.sc.sus[L_SEQ-1][dl];
                float zv = g_z63[d];
                float sz = zv / (1.f + expf(-zv));
                g_y[d] = (partial + uv63 * Dp[d]) * sz;
            }
        }
    }
    gbar();

    // P7: out_proj — 128 blocks, 2 warps per output
    if (bid < 128) {
        for (int i = t; i < D_INNER; i += NTHR) sm.op.sy[i] = g_y[i];
        __syncthreads();
        int e = bid * 8 + (warp >> 1);
        int half = warp & 1;
        const float4* wr  = (const float4*)(Wo + (size_t)e * D_INNER) + half * 256;
        const float4* syp = ((const float4*)sm.op.sy) + half * 256;
        float a = 0.f;
        #pragma unroll
        for (int i = 0; i < 8; i++) {
            int j = i * 32 + lane;
            float4 w = wr[j];
            float4 s = syp[j];
            a += w.x*s.x + w.y*s.y + w.z*s.z + w.w*s.w;
        }
        #pragma unroll
        for (int off = 16; off > 0; off >>= 1) a += __shfl_xor_sync(0xffffffffu, a, off);
        if (lane == 0) sm.op.sp[warp] = a;
        __syncthreads();
        if (t < 8) g_ctx[bid * 8 + t] = sm.op.sp[2*t] + sm.op.sp[2*t + 1];
    }
    gbar();

    // P8: layernorm (block 0)
    if (bid == 0) {
        float v0 = g_ctx[t], v1 = g_ctx[t + NTHR];
        sm.ln.red[t] = v0 + v1; __syncthreads();
        for (int o = 256; o > 0; o >>= 1) { if (t < o) sm.ln.red[t] += sm.ln.red[t+o]; __syncthreads(); }
        float mu = sm.ln.red[0] / (float)D_MODEL;
        __syncthreads();
        float d0 = v0 - mu, d1 = v1 - mu;
        sm.ln.red[t] = d0*d0 + d1*d1; __syncthreads();
        for (int o = 256; o > 0; o >>= 1) { if (t < o) sm.ln.red[t] += sm.ln.red[t+o]; __syncthreads(); }
        float rs = rsqrtf(sm.ln.red[0] / (float)D_MODEL + EPS_LN);
        outF[t]        = d0 * rs * lng[t]        + lnb[t];
        outF[t + NTHR] = d1 * rs * lng[t + NTHR] + lnb[t + NTHR];
    }
}

// ---------------- launch ----------------
extern "C" void kernel_launch(void* const* d_in, const int* in_sizes, int n_in,
                              void* d_out, int out_size) {
    const float* query    = (const float*)d_in[0];
    const float* memory   = (const float*)d_in[1];
    const int*   usage    = (const int*)  d_in[2];
    const float* in_proj  = (const float*)d_in[3];
    const float* conv_w   = (const float*)d_in[4];
    const float* conv_b   = (const float*)d_in[5];
    const float* x_proj   = (const float*)d_in[6];
    const float* dt_proj  = (const float*)d_in[7];
    const float* dt_b     = (const float*)d_in[8];
    const float* A_log    = (const float*)d_in[9];
    const float* Dp       = (const float*)d_in[10];
    const float* out_proj = (const float*)d_in[11];
    const float* ln_g     = (const float*)d_in[12];
    const float* ln_b     = (const float*)d_in[13];

    float* outF = (float*)d_out;
    bool has_usage = (out_size >= D_MODEL + MEM_SIZE);
    float* outU = outF + D_MODEL;
    int hasU = has_usage ? 1 : 0;
    float* outUp = has_usage ? outU : (float*)nullptr;

    k_sims<<<MEM_SIZE/64, 256>>>(memory, query, usage, outUp, hasU);   // #1
    k_mid<<<NBLK, GTHR>>>(memory, in_proj, conv_w, conv_b,             // #2
                          usage, outUp, hasU);
    k_rest<<<NBLK, NTHR>>>(x_proj, dt_proj, dt_b, A_log, Dp,           // #3
                           out_proj, ln_g, ln_b, outF);
}